// round 4
// baseline (speedup 1.0000x reference)
#include <cuda_runtime.h>
#include <cstdint>

// Fixed shapes per reference
#define NN     50000
#define IN_F   256
#define H_F    128
#define OUT_F  64
#define EMAX   800000

// ---------------------------------------------------------------------------
// Static device scratch (no allocation allowed).
// ---------------------------------------------------------------------------
__device__ __align__(16) float g_t[(size_t)NN * H_F];   // GEMM output buffer
__device__ __align__(16) float g_a[(size_t)NN * H_F];   // hidden activations
__device__ float g_dinv[NN];
__device__ int   g_cnt[NN];      // histogram, then scatter counters
__device__ int   g_off[NN + 1];  // CSR offsets (grouped by dst)
__device__ int   g_col[EMAX];    // CSR src indices
__device__ int   g_is64;         // edge_index element width flag

// ---------------------------------------------------------------------------
// Edge width autodetect: int64 values < 2^32 => every odd int32 word is 0.
// ---------------------------------------------------------------------------
__global__ void detect_kernel(const int* __restrict__ ei32) {
    if (threadIdx.x == 0 && blockIdx.x == 0) {
        int allzero = 1;
        for (int i = 0; i < 64; i++)
            if (ei32[2 * i + 1] != 0) { allzero = 0; break; }
        g_is64 = allzero;
    }
}

__device__ __forceinline__ int edge_src(const int* ei, int E, int e) {
    return g_is64 ? ei[2 * (size_t)e] : ei[(size_t)e];
}
__device__ __forceinline__ int edge_dst(const int* ei, int E, int e) {
    return g_is64 ? ei[2 * ((size_t)E + e)] : ei[(size_t)E + e];
}

// ---------------------------------------------------------------------------
// CSR build: zero -> histogram(dst) -> scan(+dinv) -> scatter(src)
// ---------------------------------------------------------------------------
__global__ void zero_cnt_kernel(int n) {
    int i = blockIdx.x * blockDim.x + threadIdx.x;
    if (i < n) g_cnt[i] = 0;
}

__global__ void hist_kernel(const int* __restrict__ ei, int E) {
    int e = blockIdx.x * blockDim.x + threadIdx.x;
    if (e >= E) return;
    int d = edge_dst(ei, E, e);
    if ((unsigned)d < (unsigned)NN) atomicAdd(&g_cnt[d], 1);
}

// Single block, 1024 threads: exclusive scan of g_cnt into g_off,
// dinv[i] = rsqrt(cnt+1) (self-loop), reset g_cnt for the scatter pass.
__global__ void scan_kernel(int n) {
    __shared__ int sums[1024];
    const int tid = threadIdx.x;
    const int CH = (n + 1023) / 1024;
    const int start = tid * CH;
    const int end = (start + CH < n) ? start + CH : n;

    int s = 0;
    for (int i = start; i < end; i++) s += g_cnt[i];
    sums[tid] = s;
    __syncthreads();
    for (int off = 1; off < 1024; off <<= 1) {
        int v = sums[tid];
        int u = (tid >= off) ? sums[tid - off] : 0;
        __syncthreads();
        sums[tid] = v + u;
        __syncthreads();
    }
    int run = (tid > 0) ? sums[tid - 1] : 0;
    for (int i = start; i < end; i++) {
        int c = g_cnt[i];
        g_off[i] = run;
        run += c;
        g_dinv[i] = rsqrtf((float)(c + 1));
        g_cnt[i] = 0;
    }
    if (tid == 1023) g_off[n] = sums[1023];
}

__global__ void scatter_kernel(const int* __restrict__ ei, int E) {
    int e = blockIdx.x * blockDim.x + threadIdx.x;
    if (e >= E) return;
    int s = edge_src(ei, E, e);
    int d = edge_dst(ei, E, e);
    if ((unsigned)s >= (unsigned)NN || (unsigned)d >= (unsigned)NN) return;
    int pos = g_off[d] + atomicAdd(&g_cnt[d], 1);
    g_col[pos] = s;
}

// ---------------------------------------------------------------------------
// Gather aggregation (no float atomics). One warp per dst node.
// Layer 1: a[d] = relu( sum_{s in N(d)} t[s]*dinv[s]*dinv[d] + t[d]*dinv[d]^2 + b1 )
// ---------------------------------------------------------------------------
__global__ void agg1_kernel(const float* __restrict__ b1, int n) {
    int gw   = (blockIdx.x * blockDim.x + threadIdx.x) >> 5;
    int lane = threadIdx.x & 31;
    if (gw >= n) return;
    const float4* __restrict__ trow = reinterpret_cast<const float4*>(g_t);

    float wd = g_dinv[gw];
    float ws = wd * wd;
    float4 v = trow[(size_t)gw * 32 + lane];  // self-loop
    float4 acc = make_float4(v.x * ws, v.y * ws, v.z * ws, v.w * ws);

    int beg = g_off[gw], end = g_off[gw + 1];
    for (int e = beg; e < end; e++) {
        int s = g_col[e];                       // warp-uniform (broadcast)
        float w = g_dinv[s] * wd;
        float4 u = trow[(size_t)s * 32 + lane];
        acc.x = fmaf(u.x, w, acc.x);
        acc.y = fmaf(u.y, w, acc.y);
        acc.z = fmaf(u.z, w, acc.z);
        acc.w = fmaf(u.w, w, acc.w);
    }
    float4 bb = reinterpret_cast<const float4*>(b1)[lane];
    acc.x = fmaxf(acc.x + bb.x, 0.f);
    acc.y = fmaxf(acc.y + bb.y, 0.f);
    acc.z = fmaxf(acc.z + bb.z, 0.f);
    acc.w = fmaxf(acc.w + bb.w, 0.f);
    reinterpret_cast<float4*>(g_a)[(size_t)gw * 32 + lane] = acc;
}

// Layer 2: out[d] = sum + b2  (64 features: 32 lanes x float2)
__global__ void agg2_kernel(const float* __restrict__ b2, float* __restrict__ out, int n) {
    int gw   = (blockIdx.x * blockDim.x + threadIdx.x) >> 5;
    int lane = threadIdx.x & 31;
    if (gw >= n) return;
    const float2* __restrict__ trow = reinterpret_cast<const float2*>(g_t);

    float wd = g_dinv[gw];
    float ws = wd * wd;
    float2 v = trow[(size_t)gw * 32 + lane];
    float2 acc = make_float2(v.x * ws, v.y * ws);

    int beg = g_off[gw], end = g_off[gw + 1];
    for (int e = beg; e < end; e++) {
        int s = g_col[e];
        float w = g_dinv[s] * wd;
        float2 u = trow[(size_t)s * 32 + lane];
        acc.x = fmaf(u.x, w, acc.x);
        acc.y = fmaf(u.y, w, acc.y);
    }
    float2 bb = reinterpret_cast<const float2*>(b2)[lane];
    acc.x += bb.x;
    acc.y += bb.y;
    reinterpret_cast<float2*>(out)[(size_t)gw * 32 + lane] = acc;
}

// ---------------------------------------------------------------------------
// SIMT fp32 GEMM: C[M,N] = A[M,K] @ B[K,N], C = g_t always, BN == N.
// Asel: 0 -> external pointer (x), 1 -> g_a.
// ---------------------------------------------------------------------------
template<int BM, int BN, int BK, int TM, int TN>
__global__ void __launch_bounds__((BM / TM) * (BN / TN))
gemm_kernel(const float* __restrict__ Aext, int Asel,
            const float* __restrict__ B, int M, int K, int N) {
    constexpr int THREADS = (BM / TM) * (BN / TN);
    const float* __restrict__ A = Asel ? (const float*)g_a : Aext;
    float* __restrict__ C = g_t;

    __shared__ float As[BK][BM + 1];   // +1 pad: conflict-free transposed stores
    __shared__ float Bs[BK][BN];
    const int tid  = threadIdx.x;
    const int row0 = blockIdx.x * BM;
    const int tr   = tid / (BN / TN);
    const int tc   = tid % (BN / TN);

    float acc[TM][TN];
#pragma unroll
    for (int m = 0; m < TM; m++)
#pragma unroll
        for (int n = 0; n < TN; n++) acc[m][n] = 0.f;

    for (int k0 = 0; k0 < K; k0 += BK) {
#pragma unroll
        for (int idx = tid; idx < BM * BK; idx += THREADS) {
            int i = idx / BK, kk = idx % BK;
            int r = row0 + i;
            As[kk][i] = (r < M) ? A[(size_t)r * K + k0 + kk] : 0.f;
        }
#pragma unroll
        for (int idx = tid; idx < BK * BN; idx += THREADS) {
            int kk = idx / BN, j = idx % BN;
            Bs[kk][j] = B[(size_t)(k0 + kk) * N + j];
        }
        __syncthreads();
#pragma unroll
        for (int kk = 0; kk < BK; kk++) {
            float a[TM], b[TN];
#pragma unroll
            for (int n = 0; n < TN; n++) b[n] = Bs[kk][tc * TN + n];
#pragma unroll
            for (int m = 0; m < TM; m++) a[m] = As[kk][tr * TM + m];
#pragma unroll
            for (int m = 0; m < TM; m++)
#pragma unroll
                for (int n = 0; n < TN; n++) acc[m][n] = fmaf(a[m], b[n], acc[m][n]);
        }
        __syncthreads();
    }
#pragma unroll
    for (int m = 0; m < TM; m++) {
        int r = row0 + tr * TM + m;
        if (r < M) {
            float4 v = make_float4(acc[m][0], acc[m][1], acc[m][2], acc[m][3]);
            *reinterpret_cast<float4*>(&C[(size_t)r * N + tc * TN]) = v;
        }
    }
}

// ---------------------------------------------------------------------------
// Launch: 9 kernels on the default stream (graph-capturable, allocation-free)
// ---------------------------------------------------------------------------
extern "C" void kernel_launch(void* const* d_in, const int* in_sizes, int n_in,
                              void* d_out, int out_size) {
    const float* x   = (const float*)d_in[0];
    const int*   ei  = (const int*)d_in[1];   // int32 edge list (auto-detect int64)
    const float* W1  = (const float*)d_in[2];
    const float* b1  = (const float*)d_in[3];
    const float* W2  = (const float*)d_in[4];
    const float* b2  = (const float*)d_in[5];
    float*       out = (float*)d_out;

    const int N = in_sizes[0] / IN_F;   // 50000
    const int E = in_sizes[1] / 2;      // 800000
    const int TB = 256;

    // edge width detect + CSR build (dst-grouped) + dinv
    detect_kernel<<<1, 32>>>(ei);
    zero_cnt_kernel<<<(N + TB - 1) / TB, TB>>>(N);
    hist_kernel<<<(E + TB - 1) / TB, TB>>>(ei, E);
    scan_kernel<<<1, 1024>>>(N);
    scatter_kernel<<<(E + TB - 1) / TB, TB>>>(ei, E);

    // layer 1: g_t = x @ W1 ; g_a = relu(agg(g_t) + b1)
    gemm_kernel<64, 128, 16, 8, 4><<<(N + 63) / 64, 256>>>(x, 0, W1, N, IN_F, H_F);
    agg1_kernel<<<(N + 7) / 8, 256>>>(b1, N);

    // layer 2: g_t = g_a @ W2 ; out = agg(g_t) + b2
    gemm_kernel<64, 64, 16, 4, 4><<<(N + 63) / 64, 256>>>(nullptr, 1, W2, N, H_F, OUT_F);
    agg2_kernel<<<(N + 7) / 8, 256>>>(b2, out, N);
}

// round 5
// speedup vs baseline: 1.4230x; 1.4230x over previous
#include <cuda_runtime.h>
#include <cstdint>

// Fixed shapes per reference
#define NN     50000
#define IN_F   256
#define H_F    128
#define OUT_F  64
#define EMAX   800000

// ---------------------------------------------------------------------------
// Static device scratch (no allocation allowed).
// ---------------------------------------------------------------------------
__device__ __align__(16) float g_t[(size_t)NN * H_F];   // GEMM output buffer
__device__ __align__(16) float g_a[(size_t)NN * H_F];   // hidden activations
__device__ float g_dinv[NN];
__device__ int   g_cnt[NN];      // histogram, then scatter counters
__device__ int   g_off[NN + 1];  // CSR offsets (grouped by dst)
__device__ int   g_col[EMAX];    // CSR src indices
__device__ int   g_bsum[256];    // block partial sums for hierarchical scan
__device__ int   g_is64;         // edge_index element width flag

// ---------------------------------------------------------------------------
// Edge width autodetect: int64 values < 2^32 => every odd int32 word is 0.
// ---------------------------------------------------------------------------
__global__ void detect_kernel(const int* __restrict__ ei32) {
    if (threadIdx.x == 0 && blockIdx.x == 0) {
        int allzero = 1;
        for (int i = 0; i < 64; i++)
            if (ei32[2 * i + 1] != 0) { allzero = 0; break; }
        g_is64 = allzero;
    }
}

__device__ __forceinline__ int edge_src(const int* ei, int E, int e) {
    return g_is64 ? ei[2 * (size_t)e] : ei[(size_t)e];
}
__device__ __forceinline__ int edge_dst(const int* ei, int E, int e) {
    return g_is64 ? ei[2 * ((size_t)E + e)] : ei[(size_t)E + e];
}

// ---------------------------------------------------------------------------
// CSR build: zero -> histogram(dst) -> hierarchical scan -> scatter(src)
// ---------------------------------------------------------------------------
__global__ void zero_cnt_kernel(int n) {
    int i = blockIdx.x * blockDim.x + threadIdx.x;
    if (i < n) g_cnt[i] = 0;
}

__global__ void hist_kernel(const int* __restrict__ ei, int E) {
    int e = blockIdx.x * blockDim.x + threadIdx.x;
    if (e >= E) return;
    int d = edge_dst(ei, E, e);
    if ((unsigned)d < (unsigned)NN) atomicAdd(&g_cnt[d], 1);
}

// Stage 1: per-256-chunk exclusive scan of g_cnt -> g_off, block total -> g_bsum
__global__ void scan_local_kernel(int n) {
    __shared__ int sh[256];
    const int tid = threadIdx.x;
    const int i = blockIdx.x * 256 + tid;
    int v = (i < n) ? g_cnt[i] : 0;
    sh[tid] = v;
    __syncthreads();
#pragma unroll
    for (int off = 1; off < 256; off <<= 1) {
        int u = (tid >= off) ? sh[tid - off] : 0;
        __syncthreads();
        sh[tid] += u;
        __syncthreads();
    }
    if (i < n) g_off[i] = sh[tid] - v;  // exclusive
    if (tid == 255) g_bsum[blockIdx.x] = sh[255];
}

// Stage 2: single block scans the (<=256) block totals, exclusive in-place
__global__ void scan_bsum_kernel(int nb) {
    __shared__ int sh[256];
    const int tid = threadIdx.x;
    int v = (tid < nb) ? g_bsum[tid] : 0;
    sh[tid] = v;
    __syncthreads();
#pragma unroll
    for (int off = 1; off < 256; off <<= 1) {
        int u = (tid >= off) ? sh[tid - off] : 0;
        __syncthreads();
        sh[tid] += u;
        __syncthreads();
    }
    if (tid < nb) g_bsum[tid] = sh[tid] - v;
}

// Stage 3: add block base, compute dinv, reset g_cnt, write g_off[n]
__global__ void scan_apply_kernel(int n) {
    int i = blockIdx.x * 256 + threadIdx.x;
    if (i >= n) return;
    int base = g_bsum[blockIdx.x];
    int c = g_cnt[i];
    int o = g_off[i] + base;
    g_off[i] = o;
    g_dinv[i] = rsqrtf((float)(c + 1));  // +1 self-loop
    g_cnt[i] = 0;
    if (i == n - 1) g_off[n] = o + c;
}

__global__ void scatter_kernel(const int* __restrict__ ei, int E) {
    int e = blockIdx.x * blockDim.x + threadIdx.x;
    if (e >= E) return;
    int s = edge_src(ei, E, e);
    int d = edge_dst(ei, E, e);
    if ((unsigned)s >= (unsigned)NN || (unsigned)d >= (unsigned)NN) return;
    int pos = g_off[d] + atomicAdd(&g_cnt[d], 1);
    g_col[pos] = s;
}

// ---------------------------------------------------------------------------
// Gather aggregation (no float atomics). One warp per dst node.
// Layer 1: a[d] = relu( sum_{s in N(d)} t[s]*dinv[s]*dinv[d] + t[d]*dinv[d]^2 + b1 )
// ---------------------------------------------------------------------------
__global__ void agg1_kernel(const float* __restrict__ b1, int n) {
    int gw   = (blockIdx.x * blockDim.x + threadIdx.x) >> 5;
    int lane = threadIdx.x & 31;
    if (gw >= n) return;
    const float4* __restrict__ trow = reinterpret_cast<const float4*>(g_t);

    float wd = g_dinv[gw];
    float ws = wd * wd;
    float4 v = trow[(size_t)gw * 32 + lane];  // self-loop
    float4 acc = make_float4(v.x * ws, v.y * ws, v.z * ws, v.w * ws);

    int beg = g_off[gw], end = g_off[gw + 1];
    for (int e = beg; e < end; e++) {
        int s = g_col[e];                       // warp-uniform (broadcast)
        float w = g_dinv[s] * wd;
        float4 u = trow[(size_t)s * 32 + lane];
        acc.x = fmaf(u.x, w, acc.x);
        acc.y = fmaf(u.y, w, acc.y);
        acc.z = fmaf(u.z, w, acc.z);
        acc.w = fmaf(u.w, w, acc.w);
    }
    float4 bb = reinterpret_cast<const float4*>(b1)[lane];
    acc.x = fmaxf(acc.x + bb.x, 0.f);
    acc.y = fmaxf(acc.y + bb.y, 0.f);
    acc.z = fmaxf(acc.z + bb.z, 0.f);
    acc.w = fmaxf(acc.w + bb.w, 0.f);
    reinterpret_cast<float4*>(g_a)[(size_t)gw * 32 + lane] = acc;
}

// Layer 2: out[d] = sum + b2  (64 features: 32 lanes x float2)
__global__ void agg2_kernel(const float* __restrict__ b2, float* __restrict__ out, int n) {
    int gw   = (blockIdx.x * blockDim.x + threadIdx.x) >> 5;
    int lane = threadIdx.x & 31;
    if (gw >= n) return;
    const float2* __restrict__ trow = reinterpret_cast<const float2*>(g_t);

    float wd = g_dinv[gw];
    float ws = wd * wd;
    float2 v = trow[(size_t)gw * 32 + lane];
    float2 acc = make_float2(v.x * ws, v.y * ws);

    int beg = g_off[gw], end = g_off[gw + 1];
    for (int e = beg; e < end; e++) {
        int s = g_col[e];
        float w = g_dinv[s] * wd;
        float2 u = trow[(size_t)s * 32 + lane];
        acc.x = fmaf(u.x, w, acc.x);
        acc.y = fmaf(u.y, w, acc.y);
    }
    float2 bb = reinterpret_cast<const float2*>(b2)[lane];
    acc.x += bb.x;
    acc.y += bb.y;
    reinterpret_cast<float2*>(out)[(size_t)gw * 32 + lane] = acc;
}

// ---------------------------------------------------------------------------
// SIMT fp32 GEMM: C[M,N] = A[M,K] @ B[K,N], C = g_t always, BN == N.
// Asel: 0 -> external pointer (x), 1 -> g_a.
// ---------------------------------------------------------------------------
template<int BM, int BN, int BK, int TM, int TN>
__global__ void __launch_bounds__((BM / TM) * (BN / TN))
gemm_kernel(const float* __restrict__ Aext, int Asel,
            const float* __restrict__ B, int M, int K, int N) {
    constexpr int THREADS = (BM / TM) * (BN / TN);
    const float* __restrict__ A = Asel ? (const float*)g_a : Aext;
    float* __restrict__ C = g_t;

    __shared__ float As[BK][BM + 1];   // +1 pad: conflict-free transposed stores
    __shared__ float Bs[BK][BN];
    const int tid  = threadIdx.x;
    const int row0 = blockIdx.x * BM;
    const int tr   = tid / (BN / TN);
    const int tc   = tid % (BN / TN);

    float acc[TM][TN];
#pragma unroll
    for (int m = 0; m < TM; m++)
#pragma unroll
        for (int n = 0; n < TN; n++) acc[m][n] = 0.f;

    for (int k0 = 0; k0 < K; k0 += BK) {
#pragma unroll
        for (int idx = tid; idx < BM * BK; idx += THREADS) {
            int i = idx / BK, kk = idx % BK;
            int r = row0 + i;
            As[kk][i] = (r < M) ? A[(size_t)r * K + k0 + kk] : 0.f;
        }
#pragma unroll
        for (int idx = tid; idx < BK * BN; idx += THREADS) {
            int kk = idx / BN, j = idx % BN;
            Bs[kk][j] = B[(size_t)(k0 + kk) * N + j];
        }
        __syncthreads();
#pragma unroll
        for (int kk = 0; kk < BK; kk++) {
            float a[TM], b[TN];
#pragma unroll
            for (int n = 0; n < TN; n++) b[n] = Bs[kk][tc * TN + n];
#pragma unroll
            for (int m = 0; m < TM; m++) a[m] = As[kk][tr * TM + m];
#pragma unroll
            for (int m = 0; m < TM; m++)
#pragma unroll
                for (int n = 0; n < TN; n++) acc[m][n] = fmaf(a[m], b[n], acc[m][n]);
        }
        __syncthreads();
    }
#pragma unroll
    for (int m = 0; m < TM; m++) {
        int r = row0 + tr * TM + m;
        if (r < M) {
            float4 v = make_float4(acc[m][0], acc[m][1], acc[m][2], acc[m][3]);
            *reinterpret_cast<float4*>(&C[(size_t)r * N + tc * TN]) = v;
        }
    }
}

// ---------------------------------------------------------------------------
// Launch (graph-capturable, allocation-free)
// ---------------------------------------------------------------------------
extern "C" void kernel_launch(void* const* d_in, const int* in_sizes, int n_in,
                              void* d_out, int out_size) {
    const float* x   = (const float*)d_in[0];
    const int*   ei  = (const int*)d_in[1];   // int32 edge list (auto-detect int64)
    const float* W1  = (const float*)d_in[2];
    const float* b1  = (const float*)d_in[3];
    const float* W2  = (const float*)d_in[4];
    const float* b2  = (const float*)d_in[5];
    float*       out = (float*)d_out;

    const int N = in_sizes[0] / IN_F;   // 50000
    const int E = in_sizes[1] / 2;      // 800000
    const int TB = 256;
    const int NB = (N + 255) / 256;     // 196 scan blocks

    // edge width detect + CSR build (dst-grouped) + dinv
    detect_kernel<<<1, 32>>>(ei);
    zero_cnt_kernel<<<(N + TB - 1) / TB, TB>>>(N);
    hist_kernel<<<(E + TB - 1) / TB, TB>>>(ei, E);
    scan_local_kernel<<<NB, 256>>>(N);
    scan_bsum_kernel<<<1, 256>>>(NB);
    scan_apply_kernel<<<NB, 256>>>(N);
    scatter_kernel<<<(E + TB - 1) / TB, TB>>>(ei, E);

    // layer 1: g_t = x @ W1 ; g_a = relu(agg(g_t) + b1)
    gemm_kernel<64, 128, 16, 8, 4><<<(N + 63) / 64, 256>>>(x, 0, W1, N, IN_F, H_F);
    agg1_kernel<<<(N + 7) / 8, 256>>>(b1, N);

    // layer 2: g_t = g_a @ W2 ; out = agg(g_t) + b2
    gemm_kernel<64, 64, 16, 4, 4><<<(N + 63) / 64, 256>>>(nullptr, 1, W2, N, H_F, OUT_F);
    agg2_kernel<<<(N + 7) / 8, 256>>>(b2, out, N);
}